// round 2
// baseline (speedup 1.0000x reference)
#include <cuda_runtime.h>
#include <math.h>

// Problem constants
#define BSZ 8
#define SEQ 1025
#define CH  3200
#define NH  25
#define HD  128
#define MROWS (BSZ*SEQ)      // 8200
#define QKVLD (3*CH)         // 9600
#define BH    (BSZ*NH)       // 200

__device__ __constant__ float kScale = 0.0883883476483184405f; // 1/sqrt(128)

// Scratch (static device globals; allocation-free contract)
static const size_t QKV_ELEMS  = (size_t)MROWS * QKVLD;        // 78,720,000
static const size_t ATTN_ELEMS = (size_t)BH * SEQ * SEQ;       // 210,125,000
static const size_t AV_ELEMS   = (size_t)MROWS * CH;           // 26,240,000

__device__ float g_qkv[(size_t)MROWS * QKVLD];
__device__ float g_attn[(size_t)BH * SEQ * SEQ];
__device__ float g_av[(size_t)MROWS * CH];

// ---------------------------------------------------------------------------
// Generic SGEMM with bias: C[M,N] = A[M,K] @ B[K,N] + bias[N]
// BM=BN=128, BK=8, TM=TN=8, 256 threads. N,K must be multiples of 4; M guarded.
// ---------------------------------------------------------------------------
__global__ __launch_bounds__(256) void sgemm_bias(
    const float* __restrict__ A, const float* __restrict__ B,
    const float* __restrict__ bias, float* __restrict__ C,
    int M, int Nn, int K)
{
    __shared__ float As[8][128];
    __shared__ float Bs[8][128];
    const int bm = blockIdx.y * 128;
    const int bn = blockIdx.x * 128;
    const int tid = threadIdx.x;
    const int tx = tid & 15;
    const int ty = tid >> 4;
    const int arow = tid >> 1;
    const int acol = (tid & 1) << 2;
    const int brow = tid >> 5;
    const int bcol = (tid & 31) << 2;

    float acc[8][8];
#pragma unroll
    for (int i = 0; i < 8; i++)
#pragma unroll
        for (int j = 0; j < 8; j++) acc[i][j] = 0.f;

    const bool a_ok = (bm + arow) < M;
    const float* Aptr = A + (size_t)(bm + arow) * K + acol;
    const float* Bptr = B + (size_t)brow * Nn + bn + bcol;

    for (int k0 = 0; k0 < K; k0 += 8) {
        float4 av = a_ok ? *(const float4*)(Aptr + k0) : make_float4(0.f, 0.f, 0.f, 0.f);
        float4 bv = *(const float4*)(Bptr + (size_t)k0 * Nn);
        As[acol + 0][arow] = av.x;
        As[acol + 1][arow] = av.y;
        As[acol + 2][arow] = av.z;
        As[acol + 3][arow] = av.w;
        *(float4*)&Bs[brow][bcol] = bv;
        __syncthreads();
#pragma unroll
        for (int kk = 0; kk < 8; kk++) {
            float ar[8], br[8];
            *(float4*)&ar[0] = *(const float4*)&As[kk][ty * 8];
            *(float4*)&ar[4] = *(const float4*)&As[kk][ty * 8 + 4];
            *(float4*)&br[0] = *(const float4*)&Bs[kk][tx * 8];
            *(float4*)&br[4] = *(const float4*)&Bs[kk][tx * 8 + 4];
#pragma unroll
            for (int i = 0; i < 8; i++)
#pragma unroll
                for (int j = 0; j < 8; j++)
                    acc[i][j] += ar[i] * br[j];
        }
        __syncthreads();
    }

#pragma unroll
    for (int i = 0; i < 8; i++) {
        int row = bm + ty * 8 + i;
        if (row >= M) continue;
        float* Crow = C + (size_t)row * Nn + bn + tx * 8;
        const float* bptr = bias + bn + tx * 8;
#pragma unroll
        for (int j = 0; j < 8; j += 4) {
            float4 v;
            v.x = acc[i][j + 0] + bptr[j + 0];
            v.y = acc[i][j + 1] + bptr[j + 1];
            v.z = acc[i][j + 2] + bptr[j + 2];
            v.w = acc[i][j + 3] + bptr[j + 3];
            *(float4*)(Crow + j) = v;
        }
    }
}

// ---------------------------------------------------------------------------
// RMSNorm in place over q (which=0) and k (which=1) slabs of g_qkv.
// One block per (row m, which). 256 threads.
// ---------------------------------------------------------------------------
__global__ __launch_bounds__(256) void rmsnorm_kernel(
    const float* __restrict__ qw, const float* __restrict__ kw)
{
    const int m = blockIdx.x;
    const int which = blockIdx.y;
    float* p = g_qkv + (size_t)m * QKVLD + (size_t)which * CH;
    const float* w = which ? kw : qw;
    const int tid = threadIdx.x;

    float ss = 0.f;
    for (int c = tid * 4; c < CH; c += 1024) {
        float4 v = *(const float4*)(p + c);
        ss += v.x * v.x + v.y * v.y + v.z * v.z + v.w * v.w;
    }
    __shared__ float red[8];
#pragma unroll
    for (int o = 16; o > 0; o >>= 1) ss += __shfl_xor_sync(0xffffffffu, ss, o);
    if ((tid & 31) == 0) red[tid >> 5] = ss;
    __syncthreads();
    if (tid < 32) {
        float s = (tid < 8) ? red[tid] : 0.f;
#pragma unroll
        for (int o = 4; o > 0; o >>= 1) s += __shfl_xor_sync(0xffffffffu, s, o);
        if (tid == 0) red[0] = s;
    }
    __syncthreads();
    const float inv = rsqrtf(red[0] * (1.0f / (float)CH) + 1e-6f);
    for (int c = tid * 4; c < CH; c += 1024) {
        float4 v = *(const float4*)(p + c);
        float4 wv = *(const float4*)(w + c);
        v.x = wv.x * (v.x * inv);
        v.y = wv.y * (v.y * inv);
        v.z = wv.z * (v.z * inv);
        v.w = wv.w * (v.w * inv);
        *(float4*)(p + c) = v;
    }
}

// ---------------------------------------------------------------------------
// Scores: S[bh,i,j] = scale * sum_d q[b,i,h,d] * k[b,j,h,d]
// 64x64 tile per block, BK=16, 256 threads, TM=TN=4.
// ---------------------------------------------------------------------------
__global__ __launch_bounds__(256) void attn_scores_kernel()
{
    const int bh = blockIdx.z;
    const int b = bh / NH, h = bh % NH;
    const int i0 = blockIdx.y * 64;
    const int j0 = blockIdx.x * 64;
    __shared__ float Qs[16][64];
    __shared__ float Ks[16][64];
    const int tid = threadIdx.x;
    const int tx = tid & 15, ty = tid >> 4;
    const int lrow = tid >> 2;
    const int lcol = (tid & 3) << 2;

    const float* qbase = g_qkv + (size_t)b * SEQ * QKVLD + (size_t)h * HD;
    const float* kbase = qbase + CH;

    float acc[4][4];
#pragma unroll
    for (int i = 0; i < 4; i++)
#pragma unroll
        for (int j = 0; j < 4; j++) acc[i][j] = 0.f;

#pragma unroll
    for (int d0 = 0; d0 < HD; d0 += 16) {
        const int qi = i0 + lrow;
        const int kj = j0 + lrow;
        float4 qv = (qi < SEQ) ? *(const float4*)(qbase + (size_t)qi * QKVLD + d0 + lcol)
                               : make_float4(0.f, 0.f, 0.f, 0.f);
        float4 kv = (kj < SEQ) ? *(const float4*)(kbase + (size_t)kj * QKVLD + d0 + lcol)
                               : make_float4(0.f, 0.f, 0.f, 0.f);
        __syncthreads();
        Qs[lcol + 0][lrow] = qv.x; Qs[lcol + 1][lrow] = qv.y;
        Qs[lcol + 2][lrow] = qv.z; Qs[lcol + 3][lrow] = qv.w;
        Ks[lcol + 0][lrow] = kv.x; Ks[lcol + 1][lrow] = kv.y;
        Ks[lcol + 2][lrow] = kv.z; Ks[lcol + 3][lrow] = kv.w;
        __syncthreads();
#pragma unroll
        for (int kk = 0; kk < 16; kk++) {
            float qr[4], kr[4];
            *(float4*)qr = *(const float4*)&Qs[kk][ty * 4];
            *(float4*)kr = *(const float4*)&Ks[kk][tx * 4];
#pragma unroll
            for (int i = 0; i < 4; i++)
#pragma unroll
                for (int j = 0; j < 4; j++)
                    acc[i][j] += qr[i] * kr[j];
        }
    }

    const float sc = kScale;
#pragma unroll
    for (int i = 0; i < 4; i++) {
        const int gi = i0 + ty * 4 + i;
        if (gi >= SEQ) continue;
        float* orow = g_attn + ((size_t)bh * SEQ + gi) * SEQ;
#pragma unroll
        for (int j = 0; j < 4; j++) {
            const int gj = j0 + tx * 4 + j;
            if (gj < SEQ) orow[gj] = acc[i][j] * sc;
        }
    }
}

// ---------------------------------------------------------------------------
// Row softmax over last dim (length SEQ). One block per (bh, i).
// ---------------------------------------------------------------------------
__global__ __launch_bounds__(256) void softmax_kernel()
{
    const int i = blockIdx.x;
    const int bh = blockIdx.y;
    float* row = g_attn + ((size_t)bh * SEQ + i) * SEQ;
    __shared__ float buf[SEQ];
    __shared__ float red[8];
    const int tid = threadIdx.x;

    float mx = -1e30f;
    for (int j = tid; j < SEQ; j += 256) {
        float v = row[j];
        buf[j] = v;
        mx = fmaxf(mx, v);
    }
#pragma unroll
    for (int o = 16; o > 0; o >>= 1) mx = fmaxf(mx, __shfl_xor_sync(0xffffffffu, mx, o));
    if ((tid & 31) == 0) red[tid >> 5] = mx;
    __syncthreads();
    if (tid < 32) {
        float m = (tid < 8) ? red[tid] : -1e30f;
#pragma unroll
        for (int o = 4; o > 0; o >>= 1) m = fmaxf(m, __shfl_xor_sync(0xffffffffu, m, o));
        if (tid == 0) red[0] = m;
    }
    __syncthreads();
    const float rmax = red[0];
    __syncthreads();

    float s = 0.f;
    for (int j = tid; j < SEQ; j += 256) {
        float e = __expf(buf[j] - rmax);
        buf[j] = e;
        s += e;
    }
#pragma unroll
    for (int o = 16; o > 0; o >>= 1) s += __shfl_xor_sync(0xffffffffu, s, o);
    if ((tid & 31) == 0) red[tid >> 5] = s;
    __syncthreads();
    if (tid < 32) {
        float v = (tid < 8) ? red[tid] : 0.f;
#pragma unroll
        for (int o = 4; o > 0; o >>= 1) v += __shfl_xor_sync(0xffffffffu, v, o);
        if (tid == 0) red[0] = v;
    }
    __syncthreads();
    const float inv = 1.0f / red[0];
    for (int j = tid; j < SEQ; j += 256) row[j] = buf[j] * inv;
}

// ---------------------------------------------------------------------------
// PV: av[b,i,h,d] = sum_j P[bh,i,j] * v[b,j,h,d]
// 64(i) x 64(d) tile per block, BK=16 over j, 256 threads.
// ---------------------------------------------------------------------------
__global__ __launch_bounds__(256) void attn_pv_kernel()
{
    const int bh = blockIdx.z;
    const int b = bh / NH, h = bh % NH;
    const int i0 = blockIdx.y * 64;
    const int d0 = blockIdx.x * 64;
    __shared__ float Ps[16][64];
    __shared__ float Vs[16][64];
    const int tid = threadIdx.x;
    const int tx = tid & 15, ty = tid >> 4;
    const int lrow = tid >> 2;
    const int lcol = (tid & 3) << 2;
    const int vrow = tid >> 4;
    const int vcol = (tid & 15) << 2;

    const float* pbase = g_attn + (size_t)bh * SEQ * SEQ;
    const float* vbase = g_qkv + (size_t)b * SEQ * QKVLD + 2 * CH + (size_t)h * HD;

    float acc[4][4];
#pragma unroll
    for (int i = 0; i < 4; i++)
#pragma unroll
        for (int j = 0; j < 4; j++) acc[i][j] = 0.f;

    for (int j0 = 0; j0 < SEQ; j0 += 16) {
        const int gi = i0 + lrow;
        float pr[4];
#pragma unroll
        for (int t = 0; t < 4; t++) {
            const int gj = j0 + lcol + t;
            pr[t] = (gi < SEQ && gj < SEQ) ? pbase[(size_t)gi * SEQ + gj] : 0.f;
        }
        const int gj2 = j0 + vrow;
        float4 vv = (gj2 < SEQ) ? *(const float4*)(vbase + (size_t)gj2 * QKVLD + d0 + vcol)
                                : make_float4(0.f, 0.f, 0.f, 0.f);
        __syncthreads();
        Ps[lcol + 0][lrow] = pr[0]; Ps[lcol + 1][lrow] = pr[1];
        Ps[lcol + 2][lrow] = pr[2]; Ps[lcol + 3][lrow] = pr[3];
        *(float4*)&Vs[vrow][vcol] = vv;
        __syncthreads();
#pragma unroll
        for (int kk = 0; kk < 16; kk++) {
            float prr[4], vrr[4];
            *(float4*)prr = *(const float4*)&Ps[kk][ty * 4];
            *(float4*)vrr = *(const float4*)&Vs[kk][tx * 4];
#pragma unroll
            for (int i = 0; i < 4; i++)
#pragma unroll
                for (int j = 0; j < 4; j++)
                    acc[i][j] += prr[i] * vrr[j];
        }
    }

#pragma unroll
    for (int i = 0; i < 4; i++) {
        const int gi = i0 + ty * 4 + i;
        if (gi >= SEQ) continue;
        float* orow = g_av + (size_t)(b * SEQ + gi) * CH + (size_t)h * HD + d0;
#pragma unroll
        for (int j = 0; j < 4; j++) {
            orow[tx * 4 + j] = acc[i][j];
        }
    }
}

// ---------------------------------------------------------------------------
// Launch
// ---------------------------------------------------------------------------
extern "C" void kernel_launch(void* const* d_in, const int* in_sizes, int n_in,
                              void* d_out, int out_size)
{
    (void)in_sizes; (void)n_in; (void)out_size;
    const float* x       = (const float*)d_in[0];
    const float* qkv_w   = (const float*)d_in[1];
    const float* qkv_b   = (const float*)d_in[2];
    const float* q_norm_w= (const float*)d_in[3];
    const float* k_norm_w= (const float*)d_in[4];
    const float* proj_w  = (const float*)d_in[5];
    const float* proj_b  = (const float*)d_in[6];
    float* out = (float*)d_out;

    void* p_qkv = nullptr; void* p_attn = nullptr; void* p_av = nullptr;
    cudaGetSymbolAddress(&p_qkv, g_qkv);
    cudaGetSymbolAddress(&p_attn, g_attn);
    cudaGetSymbolAddress(&p_av, g_av);
    float* qkv = (float*)p_qkv;
    float* av  = (float*)p_av;
    (void)p_attn;

    // 1) qkv = x @ qkv_w + qkv_b : [8200,9600]
    {
        dim3 grid(QKVLD / 128, (MROWS + 127) / 128);
        sgemm_bias<<<grid, 256>>>(x, qkv_w, qkv_b, qkv, MROWS, QKVLD, CH);
    }
    // 2) RMSNorm q and k in place
    {
        dim3 grid(MROWS, 2);
        rmsnorm_kernel<<<grid, 256>>>(q_norm_w, k_norm_w);
    }
    // 3) scores
    {
        dim3 grid((SEQ + 63) / 64, (SEQ + 63) / 64, BH);
        attn_scores_kernel<<<grid, 256>>>();
    }
    // 4) softmax
    {
        dim3 grid(SEQ, BH);
        softmax_kernel<<<grid, 256>>>();
    }
    // 5) PV
    {
        dim3 grid(HD / 64, (SEQ + 63) / 64, BH);
        attn_pv_kernel<<<grid, 256>>>();
    }
    // 6) out = av @ proj_w + proj_b
    {
        dim3 grid(CH / 128, (MROWS + 127) / 128);
        sgemm_bias<<<grid, 256>>>(av, proj_w, proj_b, out, MROWS, CH, CH);
    }
}

// round 4
// speedup vs baseline: 1.7252x; 1.7252x over previous
#include <cuda_runtime.h>
#include <mma.h>
#include <math.h>

using namespace nvcuda;

// Problem constants
#define BSZ 8
#define SEQ 1025
#define SEQP 1152            // padded seq (9*128), multiple of 16
#define KPAD 1088            // 17*64 column coverage used by PV K-loop
#define CH  3200
#define NH  25
#define HD  128
#define MROWS (BSZ*SEQ)      // 8200
#define QKVLD (3*CH)         // 9600
#define BH    (BSZ*NH)       // 200

__device__ __constant__ float kScale = 0.0883883476483184405f; // 1/sqrt(128)

// Scratch (static device globals; allocation-free contract)
__device__ float g_qkv[(size_t)MROWS * QKVLD];          // 315 MB
__device__ float g_attn[(size_t)BH * SEQP * SEQP];      // ~1.06 GB (padded)
__device__ float g_av[(size_t)MROWS * CH];              // 105 MB

typedef wmma::fragment<wmma::matrix_a, 16, 16, 8, wmma::precision::tf32, wmma::row_major> FragA;
typedef wmma::fragment<wmma::matrix_b, 16, 16, 8, wmma::precision::tf32, wmma::row_major> FragB;
typedef wmma::fragment<wmma::matrix_b, 16, 16, 8, wmma::precision::tf32, wmma::col_major> FragBc;
typedef wmma::fragment<wmma::accumulator, 16, 16, 8, float> FragC;

// ---------------------------------------------------------------------------
// Big GEMM with bias (tf32 wmma): C[M,N] = A[M,K] @ B[K,N] + bias[N]
// BM=128, BN=128, BK=32. 256 threads = 8 warps, each warp 64(m) x 32(n).
// N, K multiples of 128/32; M guarded.
// ---------------------------------------------------------------------------
__global__ __launch_bounds__(256) void wgemm_bias(
    const float* __restrict__ A, const float* __restrict__ B,
    const float* __restrict__ bias, float* __restrict__ C,
    int M, int Nn, int K)
{
    __shared__ __align__(32) float As[128][40];
    __shared__ __align__(32) float Bs[32][136];
    __shared__ __align__(32) float Cs[8][16][20];   // ldm=20 (multiple of 4 floats)

    const int tid = threadIdx.x;
    const int warp = tid >> 5;
    const int lane = tid & 31;
    const int wm = warp >> 2;   // 0..1
    const int wn = warp & 3;    // 0..3
    const int bm = blockIdx.y * 128;
    const int bn = blockIdx.x * 128;

    FragC acc[4][2];
#pragma unroll
    for (int mi = 0; mi < 4; mi++)
#pragma unroll
        for (int ni = 0; ni < 2; ni++) wmma::fill_fragment(acc[mi][ni], 0.0f);

    for (int k0 = 0; k0 < K; k0 += 32) {
        // A tile 128x32
#pragma unroll
        for (int idx = tid; idx < 1024; idx += 256) {
            const int r = idx >> 3;
            const int cg = (idx & 7) << 2;
            const int gr = bm + r;
            float4 v = (gr < M) ? *(const float4*)(A + (size_t)gr * K + k0 + cg)
                                : make_float4(0.f, 0.f, 0.f, 0.f);
            float4 t;
            t.x = wmma::__float_to_tf32(v.x);
            t.y = wmma::__float_to_tf32(v.y);
            t.z = wmma::__float_to_tf32(v.z);
            t.w = wmma::__float_to_tf32(v.w);
            *(float4*)&As[r][cg] = t;
        }
        // B tile 32x128
#pragma unroll
        for (int idx = tid; idx < 1024; idx += 256) {
            const int r = idx >> 5;
            const int cg = (idx & 31) << 2;
            float4 v = *(const float4*)(B + (size_t)(k0 + r) * Nn + bn + cg);
            float4 t;
            t.x = wmma::__float_to_tf32(v.x);
            t.y = wmma::__float_to_tf32(v.y);
            t.z = wmma::__float_to_tf32(v.z);
            t.w = wmma::__float_to_tf32(v.w);
            *(float4*)&Bs[r][cg] = t;
        }
        __syncthreads();
#pragma unroll
        for (int kk = 0; kk < 32; kk += 8) {
            FragA af[4];
            FragB bf[2];
#pragma unroll
            for (int mi = 0; mi < 4; mi++)
                wmma::load_matrix_sync(af[mi], &As[wm * 64 + mi * 16][kk], 40);
#pragma unroll
            for (int ni = 0; ni < 2; ni++)
                wmma::load_matrix_sync(bf[ni], &Bs[kk][wn * 32 + ni * 16], 136);
#pragma unroll
            for (int mi = 0; mi < 4; mi++)
#pragma unroll
                for (int ni = 0; ni < 2; ni++)
                    wmma::mma_sync(acc[mi][ni], af[mi], bf[ni], acc[mi][ni]);
        }
        __syncthreads();
    }

    // Epilogue: stage each 16x16 fragment in smem, add bias, guarded store.
    const int er = lane >> 1;
    const int ec0 = (lane & 1) * 8;
#pragma unroll
    for (int mi = 0; mi < 4; mi++) {
#pragma unroll
        for (int ni = 0; ni < 2; ni++) {
            wmma::store_matrix_sync(&Cs[warp][0][0], acc[mi][ni], 20, wmma::mem_row_major);
            __syncwarp();
            const int gr = bm + wm * 64 + mi * 16 + er;
            const int gc = bn + wn * 32 + ni * 16 + ec0;
            if (gr < M) {
                float* dst = C + (size_t)gr * Nn + gc;
                const float* bp = bias + gc;
#pragma unroll
                for (int c = 0; c < 8; c++) dst[c] = Cs[warp][er][ec0 + c] + bp[c];
            }
            __syncwarp();
        }
    }
}

// ---------------------------------------------------------------------------
// RMSNorm in place over q (which=0) and k (which=1) slabs of g_qkv.
// ---------------------------------------------------------------------------
__global__ __launch_bounds__(256) void rmsnorm_kernel(
    const float* __restrict__ qw, const float* __restrict__ kw)
{
    const int m = blockIdx.x;
    const int which = blockIdx.y;
    float* p = g_qkv + (size_t)m * QKVLD + (size_t)which * CH;
    const float* w = which ? kw : qw;
    const int tid = threadIdx.x;

    float ss = 0.f;
    for (int c = tid * 4; c < CH; c += 1024) {
        float4 v = *(const float4*)(p + c);
        ss += v.x * v.x + v.y * v.y + v.z * v.z + v.w * v.w;
    }
    __shared__ float red[8];
#pragma unroll
    for (int o = 16; o > 0; o >>= 1) ss += __shfl_xor_sync(0xffffffffu, ss, o);
    if ((tid & 31) == 0) red[tid >> 5] = ss;
    __syncthreads();
    if (tid < 32) {
        float s = (tid < 8) ? red[tid] : 0.f;
#pragma unroll
        for (int o = 4; o > 0; o >>= 1) s += __shfl_xor_sync(0xffffffffu, s, o);
        if (tid == 0) red[0] = s;
    }
    __syncthreads();
    const float inv = rsqrtf(red[0] * (1.0f / (float)CH) + 1e-6f);
    for (int c = tid * 4; c < CH; c += 1024) {
        float4 v = *(const float4*)(p + c);
        float4 wv = *(const float4*)(w + c);
        v.x = wv.x * (v.x * inv);
        v.y = wv.y * (v.y * inv);
        v.z = wv.z * (v.z * inv);
        v.w = wv.w * (v.w * inv);
        *(float4*)(p + c) = v;
    }
}

// ---------------------------------------------------------------------------
// Scores (tf32 wmma): S[bh,i,j] = sum_d (scale*q[b,i,h,d]) * k[b,j,h,d]
// BM=128 (4 warps), BN=64 (2 warps), warp = 32x32, K=128 in BK=32 steps.
// Stores unguarded into padded g_attn [SEQP x SEQP].
// ---------------------------------------------------------------------------
__global__ __launch_bounds__(256) void attn_scores_wmma()
{
    __shared__ __align__(32) float Qs[128][40];
    __shared__ __align__(32) float Ks[64][40];

    const int bh = blockIdx.z;
    const int b = bh / NH, h = bh % NH;
    const int i0 = blockIdx.y * 128;
    const int j0 = blockIdx.x * 64;
    const int tid = threadIdx.x;
    const int warp = tid >> 5;
    const int wm = warp >> 1;   // 0..3
    const int wn = warp & 1;    // 0..1

    const float* qbase = g_qkv + (size_t)b * SEQ * QKVLD + (size_t)h * HD;
    const float* kbase = qbase + CH;

    FragC acc[2][2];
#pragma unroll
    for (int mi = 0; mi < 2; mi++)
#pragma unroll
        for (int ni = 0; ni < 2; ni++) wmma::fill_fragment(acc[mi][ni], 0.0f);

    const float sc = kScale;
#pragma unroll
    for (int d0 = 0; d0 < HD; d0 += 32) {
        // Q tile 128x32 (scaled)
#pragma unroll
        for (int idx = tid; idx < 1024; idx += 256) {
            const int r = idx >> 3;
            const int cg = (idx & 7) << 2;
            const int gi = i0 + r;
            float4 v = (gi < SEQ) ? *(const float4*)(qbase + (size_t)gi * QKVLD + d0 + cg)
                                  : make_float4(0.f, 0.f, 0.f, 0.f);
            float4 t;
            t.x = wmma::__float_to_tf32(v.x * sc);
            t.y = wmma::__float_to_tf32(v.y * sc);
            t.z = wmma::__float_to_tf32(v.z * sc);
            t.w = wmma::__float_to_tf32(v.w * sc);
            *(float4*)&Qs[r][cg] = t;
        }
        // K tile 64x32
#pragma unroll
        for (int idx = tid; idx < 512; idx += 256) {
            const int r = idx >> 3;
            const int cg = (idx & 7) << 2;
            const int gj = j0 + r;
            float4 v = (gj < SEQ) ? *(const float4*)(kbase + (size_t)gj * QKVLD + d0 + cg)
                                  : make_float4(0.f, 0.f, 0.f, 0.f);
            float4 t;
            t.x = wmma::__float_to_tf32(v.x);
            t.y = wmma::__float_to_tf32(v.y);
            t.z = wmma::__float_to_tf32(v.z);
            t.w = wmma::__float_to_tf32(v.w);
            *(float4*)&Ks[r][cg] = t;
        }
        __syncthreads();
#pragma unroll
        for (int kk = 0; kk < 32; kk += 8) {
            FragA af[2];
            FragBc bf[2];
#pragma unroll
            for (int mi = 0; mi < 2; mi++)
                wmma::load_matrix_sync(af[mi], &Qs[wm * 32 + mi * 16][kk], 40);
#pragma unroll
            for (int ni = 0; ni < 2; ni++)
                wmma::load_matrix_sync(bf[ni], &Ks[wn * 32 + ni * 16][kk], 40);
#pragma unroll
            for (int mi = 0; mi < 2; mi++)
#pragma unroll
                for (int ni = 0; ni < 2; ni++)
                    wmma::mma_sync(acc[mi][ni], af[mi], bf[ni], acc[mi][ni]);
        }
        __syncthreads();
    }

    float* obase = g_attn + (size_t)bh * SEQP * SEQP;
#pragma unroll
    for (int mi = 0; mi < 2; mi++)
#pragma unroll
        for (int ni = 0; ni < 2; ni++) {
            float* dst = obase + (size_t)(i0 + wm * 32 + mi * 16) * SEQP
                         + (j0 + wn * 32 + ni * 16);
            wmma::store_matrix_sync(dst, acc[mi][ni], SEQP, wmma::mem_row_major);
        }
}

// ---------------------------------------------------------------------------
// Row softmax (padded layout). Zeros padded cols [SEQ, KPAD) for PV.
// ---------------------------------------------------------------------------
__global__ __launch_bounds__(256) void softmax_kernel()
{
    const int i = blockIdx.x;
    const int bh = blockIdx.y;
    float* row = g_attn + ((size_t)bh * SEQP + i) * SEQP;
    __shared__ float buf[SEQ];
    __shared__ float red[8];
    const int tid = threadIdx.x;

    float mx = -1e30f;
    for (int j = tid; j < SEQ; j += 256) {
        float v = row[j];
        buf[j] = v;
        mx = fmaxf(mx, v);
    }
#pragma unroll
    for (int o = 16; o > 0; o >>= 1) mx = fmaxf(mx, __shfl_xor_sync(0xffffffffu, mx, o));
    if ((tid & 31) == 0) red[tid >> 5] = mx;
    __syncthreads();
    if (tid < 32) {
        float m = (tid < 8) ? red[tid] : -1e30f;
#pragma unroll
        for (int o = 4; o > 0; o >>= 1) m = fmaxf(m, __shfl_xor_sync(0xffffffffu, m, o));
        if (tid == 0) red[0] = m;
    }
    __syncthreads();
    const float rmax = red[0];
    __syncthreads();

    float s = 0.f;
    for (int j = tid; j < SEQ; j += 256) {
        float e = __expf(buf[j] - rmax);
        buf[j] = e;
        s += e;
    }
#pragma unroll
    for (int o = 16; o > 0; o >>= 1) s += __shfl_xor_sync(0xffffffffu, s, o);
    if ((tid & 31) == 0) red[tid >> 5] = s;
    __syncthreads();
    if (tid < 32) {
        float v = (tid < 8) ? red[tid] : 0.f;
#pragma unroll
        for (int o = 4; o > 0; o >>= 1) v += __shfl_xor_sync(0xffffffffu, v, o);
        if (tid == 0) red[0] = v;
    }
    __syncthreads();
    const float inv = 1.0f / red[0];
    for (int j = tid; j < SEQ; j += 256) row[j] = buf[j] * inv;
    for (int j = SEQ + tid; j < KPAD; j += 256) row[j] = 0.f;
}

// ---------------------------------------------------------------------------
// PV (tf32 wmma): av[b,i,h,:] = sum_j P[bh,i,j] * v[b,j,h,:]
// BM=128 (2 warps x 64), BN=128=HD (4 warps x 32), K over KPAD in 32 steps.
// ---------------------------------------------------------------------------
__global__ __launch_bounds__(256) void attn_pv_wmma()
{
    __shared__ __align__(32) float Ps[128][40];
    __shared__ __align__(32) float Vs[32][136];
    __shared__ __align__(32) float Cs[8][16][20];   // ldm=20 (multiple of 4 floats)

    const int bh = blockIdx.y;
    const int b = bh / NH, h = bh % NH;
    const int i0 = blockIdx.x * 128;
    const int tid = threadIdx.x;
    const int warp = tid >> 5;
    const int lane = tid & 31;
    const int wm = warp >> 2;   // 0..1
    const int wn = warp & 3;    // 0..3

    const float* pbase = g_attn + (size_t)bh * SEQP * SEQP;
    const float* vbase = g_qkv + (size_t)b * SEQ * QKVLD + 2 * CH + (size_t)h * HD;

    FragC acc[4][2];
#pragma unroll
    for (int mi = 0; mi < 4; mi++)
#pragma unroll
        for (int ni = 0; ni < 2; ni++) wmma::fill_fragment(acc[mi][ni], 0.0f);

    for (int k0 = 0; k0 < KPAD; k0 += 32) {
        // P tile 128x32 (rows within SEQP, cols < KPAD: all valid in padded buf)
#pragma unroll
        for (int idx = tid; idx < 1024; idx += 256) {
            const int r = idx >> 3;
            const int cg = (idx & 7) << 2;
            float4 v = *(const float4*)(pbase + (size_t)(i0 + r) * SEQP + k0 + cg);
            float4 t;
            t.x = wmma::__float_to_tf32(v.x);
            t.y = wmma::__float_to_tf32(v.y);
            t.z = wmma::__float_to_tf32(v.z);
            t.w = wmma::__float_to_tf32(v.w);
            *(float4*)&Ps[r][cg] = t;
        }
        // V tile 32x128
#pragma unroll
        for (int idx = tid; idx < 1024; idx += 256) {
            const int r = idx >> 5;
            const int cg = (idx & 31) << 2;
            const int gj = k0 + r;
            float4 v = (gj < SEQ) ? *(const float4*)(vbase + (size_t)gj * QKVLD + cg)
                                  : make_float4(0.f, 0.f, 0.f, 0.f);
            float4 t;
            t.x = wmma::__float_to_tf32(v.x);
            t.y = wmma::__float_to_tf32(v.y);
            t.z = wmma::__float_to_tf32(v.z);
            t.w = wmma::__float_to_tf32(v.w);
            *(float4*)&Vs[r][cg] = t;
        }
        __syncthreads();
#pragma unroll
        for (int kk = 0; kk < 32; kk += 8) {
            FragA af[4];
            FragB bf[2];
#pragma unroll
            for (int mi = 0; mi < 4; mi++)
                wmma::load_matrix_sync(af[mi], &Ps[wm * 64 + mi * 16][kk], 40);
#pragma unroll
            for (int ni = 0; ni < 2; ni++)
                wmma::load_matrix_sync(bf[ni], &Vs[kk][wn * 32 + ni * 16], 136);
#pragma unroll
            for (int mi = 0; mi < 4; mi++)
#pragma unroll
                for (int ni = 0; ni < 2; ni++)
                    wmma::mma_sync(acc[mi][ni], af[mi], bf[ni], acc[mi][ni]);
        }
        __syncthreads();
    }

    const int er = lane >> 1;
    const int ec0 = (lane & 1) * 8;
#pragma unroll
    for (int mi = 0; mi < 4; mi++) {
#pragma unroll
        for (int ni = 0; ni < 2; ni++) {
            wmma::store_matrix_sync(&Cs[warp][0][0], acc[mi][ni], 20, wmma::mem_row_major);
            __syncwarp();
            const int gi = i0 + wm * 64 + mi * 16 + er;
            const int gc = wn * 32 + ni * 16 + ec0;
            if (gi < SEQ) {
                float* dst = g_av + (size_t)(b * SEQ + gi) * CH + (size_t)h * HD + gc;
#pragma unroll
                for (int c = 0; c < 8; c++) dst[c] = Cs[warp][er][ec0 + c];
            }
            __syncwarp();
        }
    }
}

// ---------------------------------------------------------------------------
// Launch
// ---------------------------------------------------------------------------
extern "C" void kernel_launch(void* const* d_in, const int* in_sizes, int n_in,
                              void* d_out, int out_size)
{
    (void)in_sizes; (void)n_in; (void)out_size;
    const float* x        = (const float*)d_in[0];
    const float* qkv_w    = (const float*)d_in[1];
    const float* qkv_b    = (const float*)d_in[2];
    const float* q_norm_w = (const float*)d_in[3];
    const float* k_norm_w = (const float*)d_in[4];
    const float* proj_w   = (const float*)d_in[5];
    const float* proj_b   = (const float*)d_in[6];
    float* out = (float*)d_out;

    void* p_qkv = nullptr; void* p_av = nullptr;
    cudaGetSymbolAddress(&p_qkv, g_qkv);
    cudaGetSymbolAddress(&p_av, g_av);
    float* qkv = (float*)p_qkv;
    float* av  = (float*)p_av;

    // 1) qkv = x @ qkv_w + qkv_b : [8200, 9600], K=3200
    {
        dim3 grid(QKVLD / 128, (MROWS + 127) / 128);
        wgemm_bias<<<grid, 256>>>(x, qkv_w, qkv_b, qkv, MROWS, QKVLD, CH);
    }
    // 2) RMSNorm q and k in place
    {
        dim3 grid(MROWS, 2);
        rmsnorm_kernel<<<grid, 256>>>(q_norm_w, k_norm_w);
    }
    // 3) scores into padded g_attn (17 x-tiles of 64 cover 1025..1088 cols)
    {
        dim3 g(17, SEQP / 128, BH);
        attn_scores_wmma<<<g, 256>>>();
    }
    // 4) softmax (+ zero pad cols)
    {
        dim3 grid(SEQ, BH);
        softmax_kernel<<<grid, 256>>>();
    }
    // 5) PV
    {
        dim3 grid(SEQP / 128, BH);
        attn_pv_wmma<<<grid, 256>>>();
    }
    // 6) out = av @ proj_w + proj_b : [8200, 3200], K=3200
    {
        dim3 grid(CH / 128, (MROWS + 127) / 128);
        wgemm_bias<<<grid, 256>>>(av, proj_w, proj_b, out, MROWS, CH, CH);
    }
}